// round 16
// baseline (speedup 1.0000x reference)
#include <cuda_runtime.h>
#include <cstdint>

#define T_TOT   512
#define NF      16
#define CH      4
#define NCHUNK  (T_TOT / CH)         // 128
#define XROW    20                    // 16 floats + 4 pad
#define TILE_F  (64 * XROW)           // 64 rows: row = t*16 + b  (16 batches)
#define TILE_B  (TILE_F * 4)

using u64 = unsigned long long;

#define PACK2(d, lo, hi)   asm("mov.b64 %0, {%1, %2};" : "=l"(d) : "f"(lo), "f"(hi))
#define UNPACK2(lo, hi, s) asm("mov.b64 {%0, %1}, %2;" : "=f"(lo), "=f"(hi) : "l"(s))
#define FMA2(d, a, b, c)   asm("fma.rn.f32x2 %0, %1, %2, %3;" : "=l"(d) : "l"(a), "l"(b), "l"(c))

#define CP_COMMIT() asm volatile("cp.async.commit_group;" ::: "memory")
#define CP_WAIT2()  asm volatile("cp.async.wait_group 2;" ::: "memory")

__device__ __forceinline__ void cp16(uint32_t smem_dst, const float* gsrc) {
    asm volatile("cp.async.ca.shared.global [%0], [%1], 16;"
                 :: "r"(smem_dst), "l"(gsrc) : "memory");
}

union Q4 { float4 f; u64 u[2]; };

__global__ void __launch_bounds__(64, 1)
gru_dual_kernel(const float* __restrict__ x,
                const float* __restrict__ w_ih,
                const float* __restrict__ w_hh,
                const float* __restrict__ b_ih,
                const float* __restrict__ b_hh,
                const float* __restrict__ fc_w,
                const float* __restrict__ fc_b,
                float* __restrict__ out)
{
    // per-warp 4-deep x ring; row = t*16 + b (t-major, 16 batches)
    __shared__ __align__(16) float xs[2][4][TILE_F];     // 40960 B

    const int tid   = threadIdx.x;
    const int wid   = tid >> 5;
    const int lane  = tid & 31;
    const int m     = lane & 3;           // gate-unit owned
    const int b     = lane >> 2;          // batch slot (0..7); sets: A=b, B=b+8
    const int batch0 = blockIdx.x * 32 + wid * 16;

    // ---- producer weights: gates {m, 4+m, 8+m}; r/z pre-halved with
    //      (b_ih+b_hh) folded; n row carries b_ih (shared by both sets) ----
    u64 wp[3][8];
    float bs[3];
    #pragma unroll
    for (int q = 0; q < 3; ++q) {
        const int g = q * 4 + m;
        const float sc = (q < 2) ? 0.5f : 1.0f;
        const float* wr = w_ih + g * NF;
        #pragma unroll
        for (int k = 0; k < 8; ++k) PACK2(wp[q][k], wr[2 * k] * sc, wr[2 * k + 1] * sc);
        bs[q] = (q < 2) ? 0.5f * (b_ih[g] + b_hh[g]) : b_ih[g];
    }

    // ---- consumer weights: r/z pre-halved (shared by both sets) ----
    float whr[4], whz[4], whn[4];
    #pragma unroll
    for (int k = 0; k < 4; ++k) {
        whr[k] = 0.5f * w_hh[m * 4 + k];
        whz[k] = 0.5f * w_hh[(4 + m) * 4 + k];
        whn[k] = w_hh[(8 + m) * 4 + k];
    }
    const float bhn = b_hh[8 + m];
    const float fw0 = fc_w[0], fw1 = fc_w[1], fw2 = fc_w[2], fw3 = fc_w[3];
    const float fb  = fc_b[0];

    // two independent recurrence states
    float h0A = 0.f, h1A = 0.f, h2A = 0.f, h3A = 0.f, hownA = 0.f;
    float h0B = 0.f, h1B = 0.f, h2B = 0.f, h3B = 0.f, hownB = 0.f;
    const int src = lane & 28;

    // ---- async x staging: 256 float4/chunk, 8 per lane ----
    const float* gp[8];
    uint32_t dq[8];
    const uint32_t sbase = (uint32_t)__cvta_generic_to_shared(&xs[wid][0][0]);
    #pragma unroll
    for (int j = 0; j < 8; ++j) {
        const int idx = lane + 32 * j;
        const int f = idx & 3, bb = (idx >> 2) & 15, t = idx >> 6;
        gp[j] = x + ((size_t)(batch0 + bb) * T_TOT + t) * NF + f * 4;
        dq[j] = sbase + (uint32_t)((t * 16 + bb) * XROW + f * 4) * 4;
    }

    auto issue = [&](int c) {
        if (c < NCHUNK) {
            const uint32_t boff = (uint32_t)(c & 3) * TILE_B;
            #pragma unroll
            for (int j = 0; j < 8; ++j)
                cp16(dq[j] + boff, gp[j] + (size_t)c * (CH * NF));
        }
        CP_COMMIT();
    };

    // one gate-dot triple from a row pointer
    auto dot3 = [&](const float* r, float* g3) {
        Q4 q0 = *(const Q4*)(r);
        Q4 q1 = *(const Q4*)(r + 4);
        Q4 q2 = *(const Q4*)(r + 8);
        Q4 q3 = *(const Q4*)(r + 12);
        u64 a0, a1, a2;
        PACK2(a0, bs[0], 0.0f); PACK2(a1, bs[1], 0.0f); PACK2(a2, bs[2], 0.0f);
        FMA2(a0, q0.u[0], wp[0][0], a0); FMA2(a1, q0.u[0], wp[1][0], a1); FMA2(a2, q0.u[0], wp[2][0], a2);
        FMA2(a0, q0.u[1], wp[0][1], a0); FMA2(a1, q0.u[1], wp[1][1], a1); FMA2(a2, q0.u[1], wp[2][1], a2);
        FMA2(a0, q1.u[0], wp[0][2], a0); FMA2(a1, q1.u[0], wp[1][2], a1); FMA2(a2, q1.u[0], wp[2][2], a2);
        FMA2(a0, q1.u[1], wp[0][3], a0); FMA2(a1, q1.u[1], wp[1][3], a1); FMA2(a2, q1.u[1], wp[2][3], a2);
        FMA2(a0, q2.u[0], wp[0][4], a0); FMA2(a1, q2.u[0], wp[1][4], a1); FMA2(a2, q2.u[0], wp[2][4], a2);
        FMA2(a0, q2.u[1], wp[0][5], a0); FMA2(a1, q2.u[1], wp[1][5], a1); FMA2(a2, q2.u[1], wp[2][5], a2);
        FMA2(a0, q3.u[0], wp[0][6], a0); FMA2(a1, q3.u[0], wp[1][6], a1); FMA2(a2, q3.u[0], wp[2][6], a2);
        FMA2(a0, q3.u[1], wp[0][7], a0); FMA2(a1, q3.u[1], wp[1][7], a1); FMA2(a2, q3.u[1], wp[2][7], a2);
        float lo, hi;
        UNPACK2(lo, hi, a0); g3[0] = lo + hi;
        UNPACK2(lo, hi, a1); g3[1] = lo + hi;
        UNPACK2(lo, hi, a2); g3[2] = lo + hi;
    };

    // standalone produce for both sets (prologue)
    auto produce = [&](int c, float (&gA)[12], float (&gB)[12]) {
        const float* base = xs[wid][c & 3] + b * XROW;
        #pragma unroll
        for (int t = 0; t < CH; ++t) {
            dot3(base + t * 16 * XROW, &gA[t * 3]);
            dot3(base + t * 16 * XROW + 8 * XROW, &gB[t * 3]);
        }
    };

    // ---- FUSED dual-chain chunk: consume A&B, produce next chunk A&B ----
    auto fused2 = [&](const float (&cA)[12], const float (&cB)[12],
                      int pc, float (&pA)[12], float (&pB)[12]) {
        const float* pbase = xs[wid][pc & 3] + b * XROW;
        #pragma unroll
        for (int s = 0; s < CH; ++s) {
            const float* rA = pbase + s * 16 * XROW;

            // consume part 1: GEMVs + gate polys, A and B interleaved
            const float grA = cA[s*3+0], gzA = cA[s*3+1], gnA = cA[s*3+2];
            const float grB = cB[s*3+0], gzB = cB[s*3+1], gnB = cB[s*3+2];

            float yrA = fmaf(whr[1], h1A, fmaf(whr[0], h0A, grA)) + fmaf(whr[3], h3A, whr[2] * h2A);
            float yrB = fmaf(whr[1], h1B, fmaf(whr[0], h0B, grB)) + fmaf(whr[3], h3B, whr[2] * h2B);
            float yzA = fmaf(whz[1], h1A, fmaf(whz[0], h0A, gzA)) + fmaf(whz[3], h3A, whz[2] * h2A);
            float yzB = fmaf(whz[1], h1B, fmaf(whz[0], h0B, gzB)) + fmaf(whz[3], h3B, whz[2] * h2B);
            float ghnA = fmaf(whn[1], h1A, fmaf(whn[0], h0A, bhn)) + fmaf(whn[3], h3A, whn[2] * h2A);
            float ghnB = fmaf(whn[1], h1B, fmaf(whn[0], h0B, bhn)) + fmaf(whn[3], h3B, whn[2] * h2B);

            float urA = yrA * yrA, urB = yrB * yrB;
            float prA = fmaf(urA, fmaf(urA, -0.05396825f, 0.13333333f), -0.33333333f);
            float prB = fmaf(urB, fmaf(urB, -0.05396825f, 0.13333333f), -0.33333333f);
            float thrA = fmaf(yrA * urA, prA, yrA);
            float thrB = fmaf(yrB * urB, prB, yrB);
            float uzA = yzA * yzA, uzB = yzB * yzB;
            float pzA = fmaf(uzA, fmaf(uzA, -0.05396825f, 0.13333333f), -0.33333333f);
            float pzB = fmaf(uzB, fmaf(uzB, -0.05396825f, 0.13333333f), -0.33333333f);
            float zgA = fmaf(fmaf(yzA * uzA, pzA, yzA), 0.5f, 0.5f);
            float zgB = fmaf(fmaf(yzB * uzB, pzB, yzB), 0.5f, 0.5f);

            // n-gate front (independent A/B): na, Pade, rcp
            float ghn2A = 0.5f * ghnA, ghn2B = 0.5f * ghnB;
            float naA = fmaf(thrA, ghn2A, gnA + ghn2A);
            float naB = fmaf(thrB, ghn2B, gnB + ghn2B);
            float unA = naA * naA, unB = naB * naB;
            float nnumA = fmaf(unA, unA + 105.f, 945.f);
            float nnumB = fmaf(unB, unB + 105.f, 945.f);
            float ndenA = fmaf(unA, fmaf(unA, 15.f, 420.f), 945.f);
            float ndenB = fmaf(unB, fmaf(unB, 15.f, 420.f), 945.f);
            float rdA = __frcp_rn(ndenA);
            float rdB = __frcp_rn(ndenB);

            // produce t=s for next chunk, both sets (fills rcp/chain stalls)
            dot3(rA, &pA[s * 3]);
            dot3(rA + 8 * XROW, &pB[s * 3]);

            // finish chains
            float ngA = (naA * nnumA) * rdA;
            float ngB = (naB * nnumB) * rdB;
            float hmA = fmaf(zgA, hownA - ngA, ngA);
            float hmB = fmaf(zgB, hownB - ngB, ngB);
            hownA = hmA; hownB = hmB;
            h0A = __shfl_sync(0xffffffffu, hmA, src | 0);
            h0B = __shfl_sync(0xffffffffu, hmB, src | 0);
            h1A = __shfl_sync(0xffffffffu, hmA, src | 1);
            h1B = __shfl_sync(0xffffffffu, hmB, src | 1);
            h2A = __shfl_sync(0xffffffffu, hmA, src | 2);
            h2B = __shfl_sync(0xffffffffu, hmB, src | 2);
            h3A = __shfl_sync(0xffffffffu, hmA, src | 3);
            h3B = __shfl_sync(0xffffffffu, hmB, src | 3);
        }
    };

    float gA0[12], gB0[12], gA1[12], gB1[12];

    // ---- prologue: fill ring 3 deep, produce chunk 0 ----
    issue(0);
    issue(1);
    issue(2);
    CP_WAIT2();            // chunk 0 landed
    __syncwarp();
    produce(0, gA0, gB0);

    #pragma unroll 1
    for (int it = 0; it < NCHUNK; it += 2) {
        issue(it + 3);
        CP_WAIT2();                       // chunk it+1 landed
        __syncwarp();
        fused2(gA0, gB0, it + 1, gA1, gB1);   // consume it, produce it+1

        issue(it + 4);
        CP_WAIT2();                       // chunk it+2 landed
        __syncwarp();
        fused2(gA1, gB1, it + 2, gA0, gB0);   // consume it+1, produce it+2
    }

    if (m == 0) {
        out[batch0 + b]     = fmaf(h3A, fw3, fmaf(h2A, fw2,
                              fmaf(h1A, fw1, fmaf(h0A, fw0, fb))));
        out[batch0 + 8 + b] = fmaf(h3B, fw3, fmaf(h2B, fw2,
                              fmaf(h1B, fw1, fmaf(h0B, fw0, fb))));
    }
}

extern "C" void kernel_launch(void* const* d_in, const int* in_sizes, int n_in,
                              void* d_out, int out_size)
{
    const float* x    = (const float*)d_in[0];
    const float* w_ih = (const float*)d_in[1];
    const float* w_hh = (const float*)d_in[2];
    const float* b_ih = (const float*)d_in[3];
    const float* b_hh = (const float*)d_in[4];
    const float* fc_w = (const float*)d_in[5];
    const float* fc_b = (const float*)d_in[6];
    float* out = (float*)d_out;

    gru_dual_kernel<<<4096 / 32, 64>>>(x, w_ih, w_hh, b_ih, b_hh, fc_w, fc_b, out);
}

// round 17
// speedup vs baseline: 2.2991x; 2.2991x over previous
#include <cuda_runtime.h>
#include <cstdint>

#define T_TOT   512
#define NF      16
#define CH      4
#define NCHUNK  (T_TOT / CH)         // 128
#define XROW    20                    // 16 floats + 4 pad
#define TILE_F  (32 * XROW)           // 32 rows (t-major: row = t*8 + b)
#define TILE_B  (TILE_F * 4)

using u64 = unsigned long long;

#define PACK2(d, lo, hi)   asm("mov.b64 %0, {%1, %2};" : "=l"(d) : "f"(lo), "f"(hi))
#define UNPACK2(lo, hi, s) asm("mov.b64 {%0, %1}, %2;" : "=f"(lo), "=f"(hi) : "l"(s))
#define FMA2(d, a, b, c)   asm("fma.rn.f32x2 %0, %1, %2, %3;" : "=l"(d) : "l"(a), "l"(b), "l"(c))
#define TANHF(d, a)        asm("tanh.approx.f32 %0, %1;" : "=f"(d) : "f"(a))

#define CP_COMMIT() asm volatile("cp.async.commit_group;" ::: "memory")
#define CP_WAIT2()  asm volatile("cp.async.wait_group 2;" ::: "memory")

__device__ __forceinline__ void cp16(uint32_t smem_dst, const float* gsrc) {
    asm volatile("cp.async.ca.shared.global [%0], [%1], 16;"
                 :: "r"(smem_dst), "l"(gsrc) : "memory");
}

union Q4 { float4 f; u64 u[2]; };

__global__ void __launch_bounds__(128, 1)
gru_mufu_kernel(const float* __restrict__ x,
                const float* __restrict__ w_ih,
                const float* __restrict__ w_hh,
                const float* __restrict__ b_ih,
                const float* __restrict__ b_hh,
                const float* __restrict__ fc_w,
                const float* __restrict__ fc_b,
                float* __restrict__ out)
{
    // per-warp 4-deep x ring; rows t-major: row = t*8 + b (conflict-free)
    __shared__ __align__(16) float xs[4][4][TILE_F];     // 40960 B

    const int tid   = threadIdx.x;
    const int wid   = tid >> 5;
    const int lane  = tid & 31;
    const int m     = lane & 3;           // gate-unit owned
    const int b     = lane >> 2;          // batch within warp (0..7)
    const int batch0 = blockIdx.x * 32 + wid * 8;

    // ---- producer weights: gates {m, 4+m, 8+m}; r/z pre-halved with
    //      (b_ih+b_hh) folded; n row carries b_ih ----
    u64 wp[3][8];
    float bs[3];
    #pragma unroll
    for (int q = 0; q < 3; ++q) {
        const int g = q * 4 + m;
        const float sc = (q < 2) ? 0.5f : 1.0f;
        const float* wr = w_ih + g * NF;
        #pragma unroll
        for (int k = 0; k < 8; ++k) PACK2(wp[q][k], wr[2 * k] * sc, wr[2 * k + 1] * sc);
        bs[q] = (q < 2) ? 0.5f * (b_ih[g] + b_hh[g]) : b_ih[g];
    }

    // ---- consumer weights: r/z pre-halved ----
    float whr[4], whz[4], whn[4];
    #pragma unroll
    for (int k = 0; k < 4; ++k) {
        whr[k] = 0.5f * w_hh[m * 4 + k];
        whz[k] = 0.5f * w_hh[(4 + m) * 4 + k];
        whn[k] = w_hh[(8 + m) * 4 + k];
    }
    const float bhn = b_hh[8 + m];
    const float fw0 = fc_w[0], fw1 = fc_w[1], fw2 = fc_w[2], fw3 = fc_w[3];
    const float fb  = fc_b[0];

    float h0 = 0.f, h1 = 0.f, h2 = 0.f, h3 = 0.f, hown = 0.f;
    const int src = lane & 28;

    // ---- async x staging: 128 float4/chunk, 4 per lane ----
    const float* gp[4];
    uint32_t dq[4];
    const uint32_t sbase = (uint32_t)__cvta_generic_to_shared(&xs[wid][0][0]);
    #pragma unroll
    for (int j = 0; j < 4; ++j) {
        const int idx = lane + 32 * j;
        const int f = idx & 3, bb = (idx >> 2) & 7, t = idx >> 5;
        gp[j] = x + ((size_t)(batch0 + bb) * T_TOT + t) * NF + f * 4;
        dq[j] = sbase + (uint32_t)((t * 8 + bb) * XROW + f * 4) * 4;
    }

    auto issue = [&](int c) {
        if (c < NCHUNK) {
            const uint32_t boff = (uint32_t)(c & 3) * TILE_B;
            #pragma unroll
            for (int j = 0; j < 4; ++j)
                cp16(dq[j] + boff, gp[j] + (size_t)c * (CH * NF));
        }
        CP_COMMIT();
    };

    // ---- standalone produce (prologue only) ----
    auto produce = [&](int c, float (&gl)[12]) {
        const float* base = xs[wid][c & 3] + b * XROW;
        #pragma unroll
        for (int t = 0; t < CH; ++t) {
            const float* r = base + t * 8 * XROW;
            Q4 q0 = *(const Q4*)(r);
            Q4 q1 = *(const Q4*)(r + 4);
            Q4 q2 = *(const Q4*)(r + 8);
            Q4 q3 = *(const Q4*)(r + 12);
            #pragma unroll
            for (int q = 0; q < 3; ++q) {
                u64 acc; PACK2(acc, bs[q], 0.0f);
                FMA2(acc, q0.u[0], wp[q][0], acc);
                FMA2(acc, q0.u[1], wp[q][1], acc);
                FMA2(acc, q1.u[0], wp[q][2], acc);
                FMA2(acc, q1.u[1], wp[q][3], acc);
                FMA2(acc, q2.u[0], wp[q][4], acc);
                FMA2(acc, q2.u[1], wp[q][5], acc);
                FMA2(acc, q3.u[0], wp[q][6], acc);
                FMA2(acc, q3.u[1], wp[q][7], acc);
                float lo, hi; UNPACK2(lo, hi, acc);
                gl[t * 3 + q] = lo + hi;
            }
        }
    };

    // ---- FUSED chunk: consume(gc) steps interleaved with produce(pc)->gpv ----
    auto fused = [&](const float (&gc)[12], int pc, float (&gpv)[12]) {
        const float* pb = xs[wid][pc & 3] + b * XROW;
        #pragma unroll
        for (int s = 0; s < CH; ++s) {
            // -- produce t=s: fire LDS early (latency buried under chain) --
            const float* r = pb + s * 8 * XROW;
            Q4 q0 = *(const Q4*)(r);
            Q4 q1 = *(const Q4*)(r + 4);
            Q4 q2 = *(const Q4*)(r + 8);
            Q4 q3 = *(const Q4*)(r + 12);

            // -- consume step s: GEMVs --
            const float gr = gc[s * 3 + 0];   // a_r/2 base (biases folded)
            const float gz = gc[s * 3 + 1];   // a_z/2 base
            const float gn = gc[s * 3 + 2];   // gi_n + b_ih_n

            float yr = fmaf(whr[1], h1, fmaf(whr[0], h0, gr))
                     + fmaf(whr[3], h3, whr[2] * h2);            // a_r/2
            float yz = fmaf(whz[1], h1, fmaf(whz[0], h0, gz))
                     + fmaf(whz[3], h3, whz[2] * h2);            // a_z/2
            float ghn = fmaf(whn[1], h1, fmaf(whn[0], h0, bhn))
                      + fmaf(whn[3], h3, whn[2] * h2);

            // -- activations on the MUFU pipe --
            float thr, thz;
            TANHF(thr, yr);                   // tanh(a_r/2)
            TANHF(thz, yz);                   // tanh(a_z/2)
            float zg = fmaf(thz, 0.5f, 0.5f); // sigmoid(a_z)

            // na = gi_n + sigmoid(a_r)*gh_n = (gn + ghn/2) + thr*(ghn/2)
            float ghn2 = 0.5f * ghn;
            float na = fmaf(thr, ghn2, gn + ghn2);
            float ng;
            TANHF(ng, na);                    // n = tanh(na)

            // -- produce t=s: 3 gate-dots (independent; fills MUFU/chain stalls) --
            u64 a0, a1, a2;
            PACK2(a0, bs[0], 0.0f);
            PACK2(a1, bs[1], 0.0f);
            PACK2(a2, bs[2], 0.0f);
            FMA2(a0, q0.u[0], wp[0][0], a0); FMA2(a1, q0.u[0], wp[1][0], a1); FMA2(a2, q0.u[0], wp[2][0], a2);
            FMA2(a0, q0.u[1], wp[0][1], a0); FMA2(a1, q0.u[1], wp[1][1], a1); FMA2(a2, q0.u[1], wp[2][1], a2);
            FMA2(a0, q1.u[0], wp[0][2], a0); FMA2(a1, q1.u[0], wp[1][2], a1); FMA2(a2, q1.u[0], wp[2][2], a2);
            FMA2(a0, q1.u[1], wp[0][3], a0); FMA2(a1, q1.u[1], wp[1][3], a1); FMA2(a2, q1.u[1], wp[2][3], a2);
            FMA2(a0, q2.u[0], wp[0][4], a0); FMA2(a1, q2.u[0], wp[1][4], a1); FMA2(a2, q2.u[0], wp[2][4], a2);
            FMA2(a0, q2.u[1], wp[0][5], a0); FMA2(a1, q2.u[1], wp[1][5], a1); FMA2(a2, q2.u[1], wp[2][5], a2);
            FMA2(a0, q3.u[0], wp[0][6], a0); FMA2(a1, q3.u[0], wp[1][6], a1); FMA2(a2, q3.u[0], wp[2][6], a2);
            FMA2(a0, q3.u[1], wp[0][7], a0); FMA2(a1, q3.u[1], wp[1][7], a1); FMA2(a2, q3.u[1], wp[2][7], a2);
            {
                float lo, hi;
                UNPACK2(lo, hi, a0); gpv[s * 3 + 0] = lo + hi;
                UNPACK2(lo, hi, a1); gpv[s * 3 + 1] = lo + hi;
                UNPACK2(lo, hi, a2); gpv[s * 3 + 2] = lo + hi;
            }

            // -- consume step s: h update + exchange --
            float hm = fmaf(zg, hown - ng, ng);
            hown = hm;
            h0 = __shfl_sync(0xffffffffu, hm, src | 0);
            h1 = __shfl_sync(0xffffffffu, hm, src | 1);
            h2 = __shfl_sync(0xffffffffu, hm, src | 2);
            h3 = __shfl_sync(0xffffffffu, hm, src | 3);
        }
    };

    float glA[12], glB[12];

    // ---- prologue: fill ring 3 deep, produce chunk 0 standalone ----
    issue(0);
    issue(1);
    issue(2);
    CP_WAIT2();            // chunk 0 landed
    __syncwarp();
    produce(0, glA);

    #pragma unroll 1
    for (int it = 0; it < NCHUNK; it += 2) {
        issue(it + 3);
        CP_WAIT2();                     // chunk it+1 landed
        __syncwarp();
        fused(glA, it + 1, glB);        // consume it, produce it+1

        issue(it + 4);
        CP_WAIT2();                     // chunk it+2 landed
        __syncwarp();
        fused(glB, it + 2, glA);        // consume it+1, produce it+2 (tail: unused)
    }

    if (m == 0) {
        out[batch0 + b] = fmaf(h3, fw3, fmaf(h2, fw2,
                          fmaf(h1, fw1, fmaf(h0, fw0, fb))));
    }
}

extern "C" void kernel_launch(void* const* d_in, const int* in_sizes, int n_in,
                              void* d_out, int out_size)
{
    const float* x    = (const float*)d_in[0];
    const float* w_ih = (const float*)d_in[1];
    const float* w_hh = (const float*)d_in[2];
    const float* b_ih = (const float*)d_in[3];
    const float* b_hh = (const float*)d_in[4];
    const float* fc_w = (const float*)d_in[5];
    const float* fc_b = (const float*)d_in[6];
    float* out = (float*)d_out;

    gru_mufu_kernel<<<4096 / 32, 128>>>(x, w_ih, w_hh, b_ih, b_hh, fc_w, fc_b, out);
}